// round 16
// baseline (speedup 1.0000x reference)
#include <cuda_runtime.h>

#define B_N 64
#define A_N 10647
#define G_N 50
#define C_N 9
#define NCHUNK 21
#define CH 512           // == NA*NTHR
#define NTHR 64
#define NA 8
#define NWC (NCHUNK * 2) // 42 warp-chunks of 256 anchors each

__device__ unsigned long long g_rmax[B_N * G_N * NWC];  // [(b*G+g)*42 + wc] packed (m, ~wc)
__device__ float g_bce[B_N * NWC];
__device__ float g_perimg[B_N];

__device__ __forceinline__ float clog(float x) { return fmaxf(__logf(x), -100.0f); }

// Kernel 1: per (batch, chunk): for each valid gt, the WARP-LOCAL max of
// r = inter/(area_p + area_g + eps) (monotonic in IoU) -> one packed key per
// (gt, warp-chunk). NO index tracking: k2 re-derives the argmax index by
// rescanning only the winning 256-anchor warp-chunk. NA=8 amortizes the per-gt
// reduce/store/loop overhead over 2x pairs vs the R15 kernel.
__global__ __launch_bounds__(NTHR, 16) void yolo_k1(const float* __restrict__ pred,
                                                    const float* __restrict__ bboxes,
                                                    const int* __restrict__ classes) {
    const int b = blockIdx.y, c = blockIdx.x;
    const int tid = threadIdx.x, lane = tid & 31, warp = tid >> 5;

    __shared__ float4 sgc[G_N];                  // compacted gt corners
    __shared__ float sga[G_N];                   // compacted area_g + eps
    __shared__ int sgid[G_N];                    // compacted -> original gt id
    __shared__ int scnt;

    if (tid == 0) scnt = 0;
    __syncthreads();

    if (tid < G_N) {
        if (classes[b * G_N + tid] != -1) {
            const float* gb = bboxes + (b * G_N + tid) * 4;
            float x1 = gb[0], y1 = gb[1], x2 = gb[2], y2 = gb[3];
            float cx = (x1 + x2) * 0.5f, cy = (y1 + y2) * 0.5f;
            float w = x2 - x1, h = y2 - y1;
            float gx1 = cx - w * 0.5f, gy1 = cy - h * 0.5f;
            float gx2 = cx + w * 0.5f, gy2 = cy + h * 0.5f;
            int p = atomicAdd(&scnt, 1);         // order-independent: keyed by sgid
            sgc[p] = make_float4(gx1, gy1, gx2, gy2);
            sga[p] = (gx2 - gx1) * (gy2 - gy1) + 1e-16f;
            sgid[p] = tid;
        }
    }
    __syncthreads();
    const int nv = scnt;

    const int base = c * CH;
    const float* pb = pred + (long long)b * A_N * 14;
    float px1[NA], py1[NA], px2[NA], py2[NA], pap[NA];
    float bce = 0.0f;

#pragma unroll
    for (int i = 0; i < NA; i++) {
        int a = base + tid + i * NTHR;
        bool ok = a < A_N;                       // only the last chunk is ragged
        int al = ok ? a : 0;
        const float* row = pb + (long long)al * 14;
        float2 p01 = *(const float2*)(row);
        float2 p23 = *(const float2*)(row + 2);
        float conf = row[4];
        float cx = p01.x, cy = p01.y, w = p23.x, h = p23.y;
        float x1 = cx - w * 0.5f, x2 = cx + w * 0.5f;
        float y1 = cy - h * 0.5f, y2 = cy + h * 0.5f;
        float ap = (x2 - x1) * (y2 - y1);
        if (!ok) { x1 = 3.0e38f; x2 = 3.0e38f; y1 = 3.0e38f; y2 = 3.0e38f; ap = 0.0f; }
        px1[i] = x1; px2[i] = x2; py1[i] = y1; py2[i] = y2; pap[i] = ap;
        if (ok) bce += -clog(1.0f - conf);
    }

    const int wc = c * 2 + warp;
    const unsigned lowk = 0xFFFFFFFFu - (unsigned)wc;   // max-key tie -> smallest wc

    for (int j = 0; j < nv; j++) {
        float4 gq = sgc[j];                      // one LDS.128
        float age = sga[j];                      // one LDS.32
        float br;
#pragma unroll
        for (int i = 0; i < NA; i++) {
            float iw = fmaxf(fminf(px2[i], gq.z) - fmaxf(px1[i], gq.x), 0.0f);
            float ih = fminf(py2[i], gq.w) - fmaxf(py1[i], gq.y);   // no clamp
            float inter = iw * ih;
            float S = pap[i] + age;
            float r = __fdividef(inter, S);      // MUFU.RCP + FMUL
            br = (i == 0) ? r : fmaxf(br, r);    // pure max chain, no selects
        }
        br = fmaxf(br, 0.0f);                    // +0: bit order == float order
        unsigned m = __reduce_max_sync(0xFFFFFFFFu, __float_as_uint(br));
        if (lane == 0)
            g_rmax[(b * G_N + sgid[j]) * NWC + wc] = ((unsigned long long)m << 32) | lowk;
    }

    // Deterministic per-warp bce0 partial sum -> global (fixed tree order).
#pragma unroll
    for (int s = 16; s; s >>= 1) bce += __shfl_xor_sync(0xFFFFFFFFu, bce, s);
    if (lane == 0) g_bce[b * NWC + wc] = bce;
}

// Kernel 2: one block (1024 thr) per batch; one warp per gt. Combine 42 warp-chunk
// keys, rescan the winning 256-anchor warp-chunk to recover the argmax index
// (exact same arithmetic + strict-> / min-offset tie-break), then the loss.
__global__ __launch_bounds__(1024) void yolo_k2(const float* __restrict__ pred,
                                                const float* __restrict__ bboxes,
                                                const int* __restrict__ classes) {
    const int b = blockIdx.x, tid = threadIdx.x;
    const int lane = tid & 31, warp = tid >> 5;
    __shared__ float stot;
    __shared__ float sper[G_N];
    __shared__ int svalid[G_N];

    if (warp == 0) {                             // tot0 = sum of 42 bce partials
        const float* bp = g_bce + b * NWC;
        float t = (lane < NWC) ? bp[lane] : 0.0f;
        if (lane + 32 < NWC) t += bp[lane + 32];
#pragma unroll
        for (int s = 16; s; s >>= 1) t += __shfl_xor_sync(0xFFFFFFFFu, t, s);
        if (lane == 0) stot = t;
    }
    __syncthreads();
    const float tot0 = stot;

    for (int g = warp; g < G_N; g += 32) {
        int cls = classes[b * G_N + g];
        if (cls == -1) {
            if (lane == 0) { sper[g] = 0.0f; svalid[g] = 0; }
            continue;
        }
        // Combine the 42 keys (coalesced); tie -> smallest wc via ~wc low word.
        const unsigned long long* kp = g_rmax + (size_t)(b * G_N + g) * NWC;
        unsigned long long k = (lane < NWC) ? kp[lane] : 0ULL;
        if (lane + 32 < NWC) { unsigned long long v = kp[lane + 32]; k = v > k ? v : k; }
#pragma unroll
        for (int s = 16; s; s >>= 1) {
            unsigned long long o = __shfl_xor_sync(0xFFFFFFFFu, k, s);
            k = o > k ? o : k;
        }
        unsigned wc = 0xFFFFFFFFu - (unsigned)(k & 0xFFFFFFFFULL);
        int cc = (int)(wc >> 1), w = (int)(wc & 1);

        // gt geometry (same math as k1's prologue)
        const float* gb = bboxes + (b * G_N + g) * 4;
        float bx1 = gb[0], by1 = gb[1], bx2 = gb[2], by2 = gb[3];
        float gcx = (bx1 + bx2) * 0.5f, gcy = (by1 + by2) * 0.5f;
        float gw = bx2 - bx1, gh = by2 - by1;
        float gx1 = gcx - gw * 0.5f, gy1 = gcy - gh * 0.5f;
        float gx2 = gcx + gw * 0.5f, gy2 = gcy + gh * 0.5f;
        float age = (gx2 - gx1) * (gy2 - gy1) + 1e-16f;

        // Rescan the winning 256-anchor warp-chunk (a = cc*CH + w*32 + lane + i*64).
        int abase = cc * CH + w * 32 + lane;
        float br = -3.0e38f;
        int bidx = abase;
#pragma unroll
        for (int i = 0; i < NA; i++) {
            int a = abase + i * NTHR;
            bool ok = a < A_N;
            int al = ok ? a : 0;
            const float* row = pred + (long long)(b * A_N + al) * 14;
            float2 p01 = *(const float2*)(row);
            float2 p23 = *(const float2*)(row + 2);
            float cx = p01.x, cy = p01.y, ww = p23.x, hh = p23.y;
            float x1 = cx - ww * 0.5f, x2 = cx + ww * 0.5f;
            float y1 = cy - hh * 0.5f, y2 = cy + hh * 0.5f;
            float ap = (x2 - x1) * (y2 - y1);
            float iw = fmaxf(fminf(x2, gx2) - fmaxf(x1, gx1), 0.0f);
            float ih = fminf(y2, gy2) - fmaxf(y1, gy1);
            float inter = iw * ih;
            float S = ap + age;
            float r = __fdividef(inter, S);
            if (!ok) r = -3.0e38f;               // pads can never win
            if (r > br) { br = r; bidx = a; }    // strict > keeps smallest slot
        }
        unsigned rb = __float_as_uint(fmaxf(br, 0.0f));
        unsigned m2 = __reduce_max_sync(0xFFFFFFFFu, rb);
        unsigned offk = (rb == m2) ? (unsigned)bidx : 0xFFFFFFFFu;
        unsigned aidx = __reduce_min_sync(0xFFFFFFFFu, offk);   // smallest tied index

        if (lane == 0) {
            const float* row = pred + (long long)(b * A_N + aidx) * 14;
            float d0 = row[0] - gcx, d1 = row[1] - gcy;
            float d2 = row[2] - gw,  d3 = row[3] - gh;
            float coord = 5.0f * ((d0 * d0 + d1 * d1) + (d2 * d2 + d3 * d3));
            float conf = row[4];
            float conf_obj = -clog(conf);
            float clsl = 0.0f;
#pragma unroll
            for (int ccl = 0; ccl < C_N; ccl++) {
                float p = row[5 + ccl];
                clsl += (ccl == cls) ? -clog(p) : -clog(1.0f - p);
            }
            float bce0b = -clog(1.0f - conf);
            float noobj = 0.5f * (tot0 - bce0b);
            sper[g] = (coord + conf_obj) + (clsl + noobj);
            svalid[g] = 1;
        }
    }
    __syncthreads();

    if (warp == 0) {                             // per_img (fixed-order shuffle tree)
        float s = (lane < G_N ? sper[lane] : 0.0f)
                + (lane + 32 < G_N ? sper[lane + 32] : 0.0f);
        int hv = (lane < G_N ? svalid[lane] : 0)
               | (lane + 32 < G_N ? svalid[lane + 32] : 0);
#pragma unroll
        for (int s2 = 16; s2; s2 >>= 1) s += __shfl_xor_sync(0xFFFFFFFFu, s, s2);
        unsigned anyv = __ballot_sync(0xFFFFFFFFu, hv);
        if (lane == 0) g_perimg[b] = anyv ? s : 0.5f * tot0;
    }
}

// Kernel 3: deterministic final sum (warp tree).
__global__ void yolo_k3(float* __restrict__ out) {
    const int tid = threadIdx.x, lane = tid & 31, warp = tid >> 5;
    __shared__ float sp[2];
    float v = g_perimg[tid];            // 64 threads, 64 batches
#pragma unroll
    for (int s = 16; s; s >>= 1) v += __shfl_xor_sync(0xFFFFFFFFu, v, s);
    if (lane == 0) sp[warp] = v;
    __syncthreads();
    if (tid == 0) out[0] = (sp[0] + sp[1]) / (float)B_N;
}

extern "C" void kernel_launch(void* const* d_in, const int* in_sizes, int n_in,
                              void* d_out, int out_size) {
    const float* pred    = (const float*)d_in[0];
    const float* bboxes  = (const float*)d_in[1];
    const int*   classes = (const int*)d_in[2];
    float* out = (float*)d_out;

    dim3 g1(NCHUNK, B_N);
    yolo_k1<<<g1, NTHR>>>(pred, bboxes, classes);
    yolo_k2<<<B_N, 1024>>>(pred, bboxes, classes);
    yolo_k3<<<1, 64>>>(out);
}

// round 17
// speedup vs baseline: 1.0569x; 1.0569x over previous
#include <cuda_runtime.h>

#define B_N 64
#define A_N 10647
#define G_N 50
#define C_N 9
#define NCHUNK 42
#define CH 256           // == NA*NTHR
#define NTHR 64
#define NA 4
#define NWC (NCHUNK * 2) // 84 warp-chunks of 128 anchors each

__device__ unsigned long long g_rmax[B_N * G_N * NWC];  // [(b*G+g)*84 + wc] packed (m, ~wc)
__device__ float g_bce[B_N * NWC];
__device__ float g_perimg[B_N];

__device__ __forceinline__ float clog(float x) { return fmaxf(__logf(x), -100.0f); }

// Kernel 1: per (batch, chunk): for each valid gt, the WARP-LOCAL max of
// r = inter/(area_p + area_g + eps) (monotonic in IoU) -> one packed key per
// (gt, warp-chunk). NO index tracking: k2 re-derives the argmax index by
// rescanning only the winning 128-anchor warp-chunk.
// Geometry pinned at the measured optimum: NA=4 / NTHR=64 / regs<=51 / ~5400 warps.
__global__ __launch_bounds__(NTHR, 20) void yolo_k1(const float* __restrict__ pred,
                                                    const float* __restrict__ bboxes,
                                                    const int* __restrict__ classes) {
    const int b = blockIdx.y, c = blockIdx.x;
    const int tid = threadIdx.x, lane = tid & 31, warp = tid >> 5;

    __shared__ float4 sgc[G_N];                  // compacted gt corners
    __shared__ float sga[G_N];                   // compacted area_g + eps
    __shared__ int sgid[G_N];                    // compacted -> original gt id
    __shared__ int scnt;

    if (tid == 0) scnt = 0;
    __syncthreads();

    if (tid < G_N) {
        if (classes[b * G_N + tid] != -1) {
            const float* gb = bboxes + (b * G_N + tid) * 4;
            float x1 = gb[0], y1 = gb[1], x2 = gb[2], y2 = gb[3];
            float cx = (x1 + x2) * 0.5f, cy = (y1 + y2) * 0.5f;
            float w = x2 - x1, h = y2 - y1;
            float gx1 = cx - w * 0.5f, gy1 = cy - h * 0.5f;
            float gx2 = cx + w * 0.5f, gy2 = cy + h * 0.5f;
            int p = atomicAdd(&scnt, 1);         // order-independent: keyed by sgid
            sgc[p] = make_float4(gx1, gy1, gx2, gy2);
            sga[p] = (gx2 - gx1) * (gy2 - gy1) + 1e-16f;
            sgid[p] = tid;
        }
    }
    __syncthreads();
    const int nv = scnt;

    const int base = c * CH;
    const float* pb = pred + (long long)b * A_N * 14;   // hoisted batch base
    float px1[NA], py1[NA], px2[NA], py2[NA], pap[NA];
    float bce = 0.0f;

#pragma unroll
    for (int i = 0; i < NA; i++) {
        int a = base + tid + i * NTHR;
        bool ok = a < A_N;                       // only the last chunk is ragged
        int al = ok ? a : 0;
        const float* row = pb + al * 14;
        float2 p01 = *(const float2*)(row);
        float2 p23 = *(const float2*)(row + 2);
        float conf = row[4];
        float cx = p01.x, cy = p01.y, w = p23.x, h = p23.y;
        float x1 = cx - w * 0.5f, x2 = cx + w * 0.5f;
        float y1 = cy - h * 0.5f, y2 = cy + h * 0.5f;
        float ap = (x2 - x1) * (y2 - y1);
        if (!ok) { x1 = 3.0e38f; x2 = 3.0e38f; y1 = 3.0e38f; y2 = 3.0e38f; ap = 0.0f; }
        px1[i] = x1; px2[i] = x2; py1[i] = y1; py2[i] = y2; pap[i] = ap;
        if (ok) bce += -clog(1.0f - conf);
    }

    const int wc = c * 2 + warp;
    const unsigned lowk = 0xFFFFFFFFu - (unsigned)wc;   // max-key tie -> smallest wc
    unsigned long long* rp = g_rmax + (size_t)b * G_N * NWC + wc;

#pragma unroll 2
    for (int j = 0; j < nv; j++) {
        float4 gq = sgc[j];                      // one LDS.128
        float age = sga[j];                      // one LDS.32
        float br;
#pragma unroll
        for (int i = 0; i < NA; i++) {
            float iw = fmaxf(fminf(px2[i], gq.z) - fmaxf(px1[i], gq.x), 0.0f);
            float ih = fminf(py2[i], gq.w) - fmaxf(py1[i], gq.y);   // no clamp
            float inter = iw * ih;
            float S = pap[i] + age;
            float r = __fdividef(inter, S);      // MUFU.RCP + FMUL
            br = (i == 0) ? r : fmaxf(br, r);    // pure max chain, no selects
        }
        br = fmaxf(br, 0.0f);                    // +0: bit order == float order
        unsigned m = __reduce_max_sync(0xFFFFFFFFu, __float_as_uint(br));
        if (lane == 0)
            rp[(size_t)sgid[j] * NWC] = ((unsigned long long)m << 32) | lowk;
    }

    // Deterministic per-warp bce0 partial sum -> global (fixed tree order).
#pragma unroll
    for (int s = 16; s; s >>= 1) bce += __shfl_xor_sync(0xFFFFFFFFu, bce, s);
    if (lane == 0) g_bce[b * NWC + wc] = bce;
}

// Kernel 2: one block (1024 thr) per batch; one warp per gt. Combine 84 warp-chunk
// keys, rescan the winning 128-anchor warp-chunk to recover the argmax index
// (exact same arithmetic + strict-> / min-offset tie-break), then the loss.
__global__ __launch_bounds__(1024) void yolo_k2(const float* __restrict__ pred,
                                                const float* __restrict__ bboxes,
                                                const int* __restrict__ classes) {
    const int b = blockIdx.x, tid = threadIdx.x;
    const int lane = tid & 31, warp = tid >> 5;
    __shared__ float stot;
    __shared__ float sper[G_N];
    __shared__ int svalid[G_N];

    if (warp == 0) {                             // tot0 = sum of 84 bce partials
        const float* bp = g_bce + b * NWC;
        float t = bp[lane] + bp[lane + 32];
        if (lane < NWC - 64) t += bp[lane + 64];
#pragma unroll
        for (int s = 16; s; s >>= 1) t += __shfl_xor_sync(0xFFFFFFFFu, t, s);
        if (lane == 0) stot = t;
    }
    __syncthreads();
    const float tot0 = stot;

    for (int g = warp; g < G_N; g += 32) {
        int cls = classes[b * G_N + g];
        if (cls == -1) {
            if (lane == 0) { sper[g] = 0.0f; svalid[g] = 0; }
            continue;
        }
        // Combine the 84 keys (coalesced); tie -> smallest wc via ~wc low word.
        const unsigned long long* kp = g_rmax + (size_t)(b * G_N + g) * NWC;
        unsigned long long k = kp[lane];
        { unsigned long long v = kp[lane + 32]; k = v > k ? v : k; }
        if (lane < NWC - 64) { unsigned long long v = kp[lane + 64]; k = v > k ? v : k; }
#pragma unroll
        for (int s = 16; s; s >>= 1) {
            unsigned long long o = __shfl_xor_sync(0xFFFFFFFFu, k, s);
            k = o > k ? o : k;
        }
        unsigned wc = 0xFFFFFFFFu - (unsigned)(k & 0xFFFFFFFFULL);
        int cc = (int)(wc >> 1), w = (int)(wc & 1);

        // gt geometry (same math as k1's prologue)
        const float* gb = bboxes + (b * G_N + g) * 4;
        float bx1 = gb[0], by1 = gb[1], bx2 = gb[2], by2 = gb[3];
        float gcx = (bx1 + bx2) * 0.5f, gcy = (by1 + by2) * 0.5f;
        float gw = bx2 - bx1, gh = by2 - by1;
        float gx1 = gcx - gw * 0.5f, gy1 = gcy - gh * 0.5f;
        float gx2 = gcx + gw * 0.5f, gy2 = gcy + gh * 0.5f;
        float age = (gx2 - gx1) * (gy2 - gy1) + 1e-16f;

        // Rescan the winning 128-anchor warp-chunk (a = cc*CH + w*32 + lane + i*64).
        int abase = cc * CH + w * 32 + lane;
        float br = -3.0e38f;
        int bidx = abase;
#pragma unroll
        for (int i = 0; i < NA; i++) {
            int a = abase + i * NTHR;
            bool ok = a < A_N;
            int al = ok ? a : 0;
            const float* row = pred + (long long)(b * A_N + al) * 14;
            float2 p01 = *(const float2*)(row);
            float2 p23 = *(const float2*)(row + 2);
            float cx = p01.x, cy = p01.y, ww = p23.x, hh = p23.y;
            float x1 = cx - ww * 0.5f, x2 = cx + ww * 0.5f;
            float y1 = cy - hh * 0.5f, y2 = cy + hh * 0.5f;
            float ap = (x2 - x1) * (y2 - y1);
            float iw = fmaxf(fminf(x2, gx2) - fmaxf(x1, gx1), 0.0f);
            float ih = fminf(y2, gy2) - fmaxf(y1, gy1);
            float inter = iw * ih;
            float S = ap + age;
            float r = __fdividef(inter, S);
            if (!ok) r = -3.0e38f;               // pads can never win
            if (r > br) { br = r; bidx = a; }    // strict > keeps smallest slot
        }
        unsigned rb = __float_as_uint(fmaxf(br, 0.0f));
        unsigned m2 = __reduce_max_sync(0xFFFFFFFFu, rb);
        unsigned offk = (rb == m2) ? (unsigned)bidx : 0xFFFFFFFFu;
        unsigned aidx = __reduce_min_sync(0xFFFFFFFFu, offk);   // smallest tied index

        if (lane == 0) {
            const float* row = pred + (long long)(b * A_N + aidx) * 14;
            float d0 = row[0] - gcx, d1 = row[1] - gcy;
            float d2 = row[2] - gw,  d3 = row[3] - gh;
            float coord = 5.0f * ((d0 * d0 + d1 * d1) + (d2 * d2 + d3 * d3));
            float conf = row[4];
            float conf_obj = -clog(conf);
            float clsl = 0.0f;
#pragma unroll
            for (int ccl = 0; ccl < C_N; ccl++) {
                float p = row[5 + ccl];
                clsl += (ccl == cls) ? -clog(p) : -clog(1.0f - p);
            }
            float bce0b = -clog(1.0f - conf);
            float noobj = 0.5f * (tot0 - bce0b);
            sper[g] = (coord + conf_obj) + (clsl + noobj);
            svalid[g] = 1;
        }
    }
    __syncthreads();

    if (warp == 0) {                             // per_img (fixed-order shuffle tree)
        float s = (lane < G_N ? sper[lane] : 0.0f)
                + (lane + 32 < G_N ? sper[lane + 32] : 0.0f);
        int hv = (lane < G_N ? svalid[lane] : 0)
               | (lane + 32 < G_N ? svalid[lane + 32] : 0);
#pragma unroll
        for (int s2 = 16; s2; s2 >>= 1) s += __shfl_xor_sync(0xFFFFFFFFu, s, s2);
        unsigned anyv = __ballot_sync(0xFFFFFFFFu, hv);
        if (lane == 0) g_perimg[b] = anyv ? s : 0.5f * tot0;
    }
}

// Kernel 3: deterministic final sum (warp tree).
__global__ void yolo_k3(float* __restrict__ out) {
    const int tid = threadIdx.x, lane = tid & 31, warp = tid >> 5;
    __shared__ float sp[2];
    float v = g_perimg[tid];            // 64 threads, 64 batches
#pragma unroll
    for (int s = 16; s; s >>= 1) v += __shfl_xor_sync(0xFFFFFFFFu, v, s);
    if (lane == 0) sp[warp] = v;
    __syncthreads();
    if (tid == 0) out[0] = (sp[0] + sp[1]) / (float)B_N;
}

extern "C" void kernel_launch(void* const* d_in, const int* in_sizes, int n_in,
                              void* d_out, int out_size) {
    const float* pred    = (const float*)d_in[0];
    const float* bboxes  = (const float*)d_in[1];
    const int*   classes = (const int*)d_in[2];
    float* out = (float*)d_out;

    dim3 g1(NCHUNK, B_N);
    yolo_k1<<<g1, NTHR>>>(pred, bboxes, classes);
    yolo_k2<<<B_N, 1024>>>(pred, bboxes, classes);
    yolo_k3<<<1, 64>>>(out);
}